// round 16
// baseline (speedup 1.0000x reference)
#include <cuda_runtime.h>
#include <cuda_bf16.h>
#include <mma.h>

using namespace nvcuda;

#define N_NODES 100000
#define N_PAD   100096                    // 128-aligned for unguarded wmma stores
#define N_EDGES 800000
#define DIM     64
#define HEADS   4
#define NBLK    ((N_NODES + 255) / 256)   // 391 scan blocks

typedef unsigned long long u64;
typedef unsigned int       u32;

// L2-resident scratch (GB300 L2 ~126MB)
__device__ float g_Q[N_PAD * DIM];
__device__ float g_K[N_PAD * DIM];
__device__ float g_V[N_PAD * DIM];

// Pre-converted operands (bf16 hi/lo split)
__device__ __nv_bfloat16 g_Wbh[3 * 64 * 64];    // W^T [m][n][k]
__device__ __nv_bfloat16 g_Wbl[3 * 64 * 64];
__device__ __nv_bfloat16 g_Ebh[N_PAD * DIM];    // E [node][k]
__device__ __nv_bfloat16 g_Ebl[N_PAD * DIM];

// CSR scratch
__device__ int g_deg[N_NODES];                   // zeroed by node_attn each run
__device__ int g_start[N_NODES];
__device__ int g_cursor[N_NODES];
__device__ int g_incl[NBLK * 256];
__device__ int g_bsum[NBLK];
__device__ int g_colS[N_EDGES];
__device__ int g_perm[N_EDGES];

// ---------------------------------------------------------------------------
// One-shot W transpose + bf16 hi/lo split. 12288 elements.
// ---------------------------------------------------------------------------
__global__ void wconv(const float* __restrict__ Wq, const float* __restrict__ Wk,
                      const float* __restrict__ Wv) {
    int idx = blockIdx.x * 256 + threadIdx.x;
    if (idx >= 3 * 4096) return;
    int m = idx >> 12, rem = idx & 4095;
    int n = rem >> 6, k = rem & 63;
    const float* W = (m == 0) ? Wq : (m == 1) ? Wk : Wv;
    float x = W[k * 64 + n];
    __nv_bfloat16 h = __float2bfloat16_rn(x);
    __nv_bfloat16 l = __float2bfloat16_rn(x - __bfloat162float(h));
    g_Wbh[idx] = h;
    g_Wbl[idx] = l;
}

// ---------------------------------------------------------------------------
// One-shot E -> bf16 hi/lo split (zero-padded to N_PAD). float2 granularity.
// ---------------------------------------------------------------------------
__global__ void econv(const float* __restrict__ E) {
    int i = blockIdx.x * 256 + threadIdx.x;        // float2 units
    if (i >= N_PAD * 32) return;
    int node = i >> 5;
    float2 x = (node < N_NODES) ? ((const float2*)E)[i] : make_float2(0.f, 0.f);
    __nv_bfloat162 h = __float22bfloat162_rn(x);
    float2 hf = __bfloat1622float2(h);
    __nv_bfloat162 l = __float22bfloat162_rn(make_float2(x.x - hf.x, x.y - hf.y));
    ((__nv_bfloat162*)g_Ebh)[i] = h;
    ((__nv_bfloat162*)g_Ebl)[i] = l;
}

// ---------------------------------------------------------------------------
// Tensor-core GEMM via wmma, m-split (blockIdx.y selects Q/K/V).
// 256 threads, 128-node tile. Pure uint4 smem fill (pre-converted operands),
// one __syncthreads, 48 MMAs, wmma store. No converts, no bounds checks.
// ---------------------------------------------------------------------------
#define AS 72
#define BS 72

__global__ __launch_bounds__(256, 2) void gemm_qkv_wmma()
{
    extern __shared__ __nv_bfloat16 sb[];
    __nv_bfloat16* Ah = sb;                    // [128][AS]
    __nv_bfloat16* Al = Ah + 128 * AS;
    __nv_bfloat16* Bh = Al + 128 * AS;         // [64][BS]
    __nv_bfloat16* Bl = Bh + 64 * BS;

    int t    = threadIdx.x;
    int w    = t >> 5;
    int m    = blockIdx.y;
    int base = blockIdx.x * 128;

    // --- A tile copy: 2048 uint4 (hi+lo), 8 per thread ---
    #pragma unroll
    for (int q = 0; q < 4; q++) {
        int v  = t + q * 256;                  // [0,1024): hi
        int r  = v >> 3, c8 = v & 7;
        *(uint4*)(Ah + r * AS + c8 * 8) = ((const uint4*)g_Ebh)[(base + r) * 8 + c8];
        *(uint4*)(Al + r * AS + c8 * 8) = ((const uint4*)g_Ebl)[(base + r) * 8 + c8];
    }
    // --- B tile copy: 1024 uint4 (hi+lo), 4 per thread ---
    #pragma unroll
    for (int q = 0; q < 2; q++) {
        int v  = t + q * 256;                  // [0,512)
        int n  = v >> 3, k8 = v & 7;
        *(uint4*)(Bh + n * BS + k8 * 8) = ((const uint4*)g_Wbh)[m * 512 + v];
        *(uint4*)(Bl + n * BS + k8 * 8) = ((const uint4*)g_Wbl)[m * 512 + v];
    }
    __syncthreads();

    wmma::fragment<wmma::matrix_a, 16, 16, 16, __nv_bfloat16, wmma::row_major>
        ah[4], al[4];
    #pragma unroll
    for (int k = 0; k < 4; k++) {
        wmma::load_matrix_sync(ah[k], Ah + (w * 16) * AS + k * 16, AS);
        wmma::load_matrix_sync(al[k], Al + (w * 16) * AS + k * 16, AS);
    }

    wmma::fragment<wmma::accumulator, 16, 16, 16, float> acc[4];
    #pragma unroll
    for (int n = 0; n < 4; n++) wmma::fill_fragment(acc[n], 0.0f);

    #pragma unroll
    for (int k = 0; k < 4; k++) {
        #pragma unroll
        for (int n = 0; n < 4; n++) {
            wmma::fragment<wmma::matrix_b, 16, 16, 16, __nv_bfloat16,
                           wmma::col_major> bh, bl;
            wmma::load_matrix_sync(bh, Bh + (n * 16) * BS + k * 16, BS);
            wmma::load_matrix_sync(bl, Bl + (n * 16) * BS + k * 16, BS);
            wmma::mma_sync(acc[n], ah[k], bh, acc[n]);
            wmma::mma_sync(acc[n], ah[k], bl, acc[n]);
            wmma::mma_sync(acc[n], al[k], bh, acc[n]);
        }
    }

    float* O = (m == 0) ? g_Q : (m == 1) ? g_K : g_V;
    #pragma unroll
    for (int n = 0; n < 4; n++)
        wmma::store_matrix_sync(O + (size_t)(base + w * 16) * 64 + n * 16,
                                acc[n], 64, wmma::mem_row_major);
}

#define SMEM_WMMA ((2 * 128 * AS + 2 * 64 * BS) * (int)sizeof(__nv_bfloat16))

// ---------------------------------------------------------------------------
// CSR build: histogram -> block scan -> fix (inline top-prefix) -> scatter
// (g_deg is zero at entry: zeroed by node_attn at the end of each run)
// ---------------------------------------------------------------------------
__global__ void hist_kernel(const int* __restrict__ rows) {
    int e = blockIdx.x * blockDim.x + threadIdx.x;
    if (e < N_EDGES) atomicAdd(&g_deg[rows[e]], 1);
}

__global__ void scan_blocks() {
    int i    = blockIdx.x * 256 + threadIdx.x;
    int lane = threadIdx.x & 31, wid = threadIdx.x >> 5;
    int v = (i < N_NODES) ? g_deg[i] : 0;
    #pragma unroll
    for (int o = 1; o < 32; o <<= 1) {
        int u = __shfl_up_sync(0xffffffffu, v, o);
        if (lane >= o) v += u;
    }
    __shared__ int ws[8];
    if (lane == 31) ws[wid] = v;
    __syncthreads();
    if (wid == 0 && lane < 8) {
        int x = ws[lane];
        #pragma unroll
        for (int o = 1; o < 8; o <<= 1) {
            int u = __shfl_up_sync(0xffu, x, o);
            if (lane >= o) x += u;
        }
        ws[lane] = x;
    }
    __syncthreads();
    if (wid > 0) v += ws[wid - 1];
    g_incl[blockIdx.x * 256 + threadIdx.x] = v;
    if (threadIdx.x == 255) g_bsum[blockIdx.x] = v;
}

__global__ void scan_fix() {
    __shared__ int s_off;
    __shared__ int ws[8];
    int t = threadIdx.x, lane = t & 31, wid = t >> 5;

    int partial = 0;
    for (int i = t; i < blockIdx.x; i += 256) partial += g_bsum[i];
    #pragma unroll
    for (int o = 16; o > 0; o >>= 1)
        partial += __shfl_down_sync(0xffffffffu, partial, o);
    if (lane == 0) ws[wid] = partial;
    __syncthreads();
    if (t == 0) {
        int tot = 0;
        #pragma unroll
        for (int k = 0; k < 8; k++) tot += ws[k];
        s_off = tot;
    }
    __syncthreads();

    int i = blockIdx.x * 256 + t;
    if (i >= N_NODES) return;
    int st = g_incl[i] + s_off - g_deg[i];
    g_start[i]  = st;
    g_cursor[i] = st;
}

__global__ void scatter_kernel(const int* __restrict__ rows,
                               const int* __restrict__ cols) {
    int e = blockIdx.x * blockDim.x + threadIdx.x;
    if (e >= N_EDGES) return;
    int r = rows[e];
    int p = atomicAdd(&g_cursor[r], 1);
    g_colS[p] = cols[e];
    g_perm[p] = e;
}

// ---------------------------------------------------------------------------
// Half-warp-per-node fused attention (R15). Also zeroes g_deg for next run.
// ---------------------------------------------------------------------------
__global__ __launch_bounds__(64) void node_attn(float* __restrict__ res,
                                                float* __restrict__ att) {
    int tid  = threadIdx.x;
    int node = blockIdx.x * 4 + (tid >> 4);
    bool vn  = node < N_NODES;
    int n = vn ? node : 0;
    int l = tid & 15;
    int h = l >> 2;
    int s = g_start[n];
    int d = vn ? g_deg[n] : 0;
    if (vn && l == 0) g_deg[n] = 0;          // restore invariant for next run
    int dmax = max(d, __shfl_xor_sync(0xffffffffu, d, 16));

    float4 q4 = *(const float4*)&g_Q[(size_t)n * DIM + l * 4];
    float4 acc = make_float4(0.f, 0.f, 0.f, 0.f);
    float norm = 0.f;
    bool leader = (l & 3) == 0;

    for (int j = 0; j < dmax; j += 4) {
        bool va[4];
        int  idx[4], cc[4];
        #pragma unroll
        for (int i = 0; i < 4; i++) {
            va[i]  = (j + i) < d;
            idx[i] = va[i] ? (s + j + i) : 0;
        }
        #pragma unroll
        for (int i = 0; i < 4; i++) cc[i] = g_colS[idx[i]];
        float4 kk[4], vv[4];
        #pragma unroll
        for (int i = 0; i < 4; i++) {
            kk[i] = *(const float4*)&g_K[(size_t)cc[i] * DIM + l * 4];
            vv[i] = *(const float4*)&g_V[(size_t)cc[i] * DIM + l * 4];
        }
        #pragma unroll
        for (int i = 0; i < 4; i++) {
            float p = kk[i].x * q4.x + kk[i].y * q4.y
                    + kk[i].z * q4.z + kk[i].w * q4.w;
            p += __shfl_xor_sync(0xffffffffu, p, 1);
            p += __shfl_xor_sync(0xffffffffu, p, 2);
            float ex = va[i] ? __expf(fminf(fmaxf(p, -10.f), 10.f)) : 0.f;
            norm += ex;
            acc.x = fmaf(ex, vv[i].x, acc.x);
            acc.y = fmaf(ex, vv[i].y, acc.y);
            acc.z = fmaf(ex, vv[i].z, acc.z);
            acc.w = fmaf(ex, vv[i].w, acc.w);
            if (va[i] && leader) att[g_perm[idx[i]] * 4 + h] = ex;
        }
    }

    float inv = 1.0f / (norm + 1e-8f);
    if (vn)
        *(float4*)&res[(size_t)n * DIM + l * 4] =
            make_float4(acc.x * inv, acc.y * inv, acc.z * inv, acc.w * inv);

    int hb = tid & 16;
    float i0 = __shfl_sync(0xffffffffu, inv, hb + 0);
    float i1 = __shfl_sync(0xffffffffu, inv, hb + 4);
    float i2 = __shfl_sync(0xffffffffu, inv, hb + 8);
    float i3 = __shfl_sync(0xffffffffu, inv, hb + 12);
    for (int jj = l; jj < d; jj += 16) {
        int e = g_perm[s + jj];
        float4 a = *(float4*)&att[e * 4];
        a.x *= i0; a.y *= i1; a.z *= i2; a.w *= i3;
        *(float4*)&att[e * 4] = a;
    }
}

// ---------------------------------------------------------------------------
extern "C" void kernel_launch(void* const* d_in, const int* in_sizes, int n_in,
                              void* d_out, int out_size) {
    const float* embeds = (const float*)d_in[0];
    const float* Wq     = (const float*)d_in[1];
    const float* Wk     = (const float*)d_in[2];
    const float* Wv     = (const float*)d_in[3];
    const int*   rows   = (const int*)d_in[4];
    const int*   cols   = (const int*)d_in[5];

    float* res = (float*)d_out;                    // [N_NODES, 64]
    float* att = (float*)d_out + N_NODES * DIM;    // [N_EDGES, 4]

    static cudaStream_t sCsr = nullptr;
    static cudaEvent_t  evFork = nullptr, evJoin = nullptr;
    if (sCsr == nullptr) {
        cudaStreamCreateWithFlags(&sCsr, cudaStreamNonBlocking);
        cudaEventCreateWithFlags(&evFork, cudaEventDisableTiming);
        cudaEventCreateWithFlags(&evJoin, cudaEventDisableTiming);
    }

    // Fork: CSR chain (rows/cols only) parallel to conversion + GEMM.
    cudaEventRecord(evFork, 0);
    cudaStreamWaitEvent(sCsr, evFork, 0);

    // Branch A (stream 0): operand pre-conversion + m-split wmma GEMM
    wconv<<<48, 256>>>(Wq, Wk, Wv);
    econv<<<(N_PAD * 32 + 255) / 256, 256>>>(embeds);
    cudaFuncSetAttribute(gemm_qkv_wmma,
                         cudaFuncAttributeMaxDynamicSharedMemorySize, SMEM_WMMA);
    dim3 gg(N_PAD / 128, 3);
    gemm_qkv_wmma<<<gg, 256, SMEM_WMMA>>>();

    // Branch B (sCsr): CSR build (no memset: g_deg restored by node_attn)
    int eb = (N_EDGES + 255) / 256;
    hist_kernel<<<eb, 256, 0, sCsr>>>(rows);
    scan_blocks<<<NBLK, 256, 0, sCsr>>>();
    scan_fix<<<NBLK, 256, 0, sCsr>>>();
    scatter_kernel<<<eb, 256, 0, sCsr>>>(rows, cols);

    // Join
    cudaEventRecord(evJoin, sCsr);
    cudaStreamWaitEvent(0, evJoin, 0);

    // fused attention: logits + softmax + aggregate + att normalize
    node_attn<<<(N_NODES + 3) / 4, 64>>>(res, att);
}

// round 17
// speedup vs baseline: 1.0078x; 1.0078x over previous
#include <cuda_runtime.h>
#include <cuda_bf16.h>
#include <mma.h>

using namespace nvcuda;

#define N_NODES 100000
#define N_PAD   100096                    // 128-aligned for unguarded wmma stores
#define N_EDGES 800000
#define DIM     64
#define HEADS   4
#define NBLK    ((N_NODES + 255) / 256)   // 391 scan blocks

typedef unsigned long long u64;
typedef unsigned int       u32;

// L2-resident scratch (GB300 L2 ~126MB; Q+K+V = 76.9MB)
__device__ float g_Q[N_PAD * DIM];
__device__ float g_K[N_PAD * DIM];
__device__ float g_V[N_PAD * DIM];

// Pre-converted weights: [m][n][k] bf16 (W^T layout), hi / lo split
__device__ __nv_bfloat16 g_Wbh[3 * 64 * 64];
__device__ __nv_bfloat16 g_Wbl[3 * 64 * 64];

// CSR scratch (g_deg: zero at entry; restored by node_attn each run)
__device__ int g_deg[N_NODES];
__device__ int g_start[N_NODES];
__device__ int g_cursor[N_NODES];
__device__ int g_incl[NBLK * 256];
__device__ int g_bsum[NBLK];
__device__ int g_colS[N_EDGES];
__device__ int g_perm[N_EDGES];

// ---------------------------------------------------------------------------
// One-shot W transpose + bf16 hi/lo split. 12288 elements.
// ---------------------------------------------------------------------------
__global__ void wconv(const float* __restrict__ Wq, const float* __restrict__ Wk,
                      const float* __restrict__ Wv) {
    int idx = blockIdx.x * 256 + threadIdx.x;
    if (idx >= 3 * 4096) return;
    int m = idx >> 12, rem = idx & 4095;
    int n = rem >> 6, k = rem & 63;
    const float* W = (m == 0) ? Wq : (m == 1) ? Wk : Wv;
    float x = W[k * 64 + n];
    __nv_bfloat16 h = __float2bfloat16_rn(x);
    __nv_bfloat16 l = __float2bfloat16_rn(x - __bfloat162float(h));
    g_Wbh[idx] = h;
    g_Wbl[idx] = l;
}

// ---------------------------------------------------------------------------
// Tensor-core QKV GEMM via wmma (bf16 two-term split, err ~2^-18).
// 256 threads (8 warps), 128-node tile. Pre-converted B matrices staged once
// with uint4 copies; A converted in-kernel (hidden under smem fill);
// A fragments register-resident across the m-loop; one __syncthreads.
// (R15-best configuration: 140.7us total.)
// ---------------------------------------------------------------------------
#define AS 72
#define BS 72

__global__ __launch_bounds__(256, 2) void gemm_qkv_wmma(const float* __restrict__ E)
{
    extern __shared__ __nv_bfloat16 sb[];
    __nv_bfloat16* Ah = sb;                    // [128][AS]
    __nv_bfloat16* Al = Ah + 128 * AS;
    __nv_bfloat16* Bh = Al + 128 * AS;         // [3][64][BS]
    __nv_bfloat16* Bl = Bh + 3 * 64 * BS;

    int t    = threadIdx.x;
    int w    = t >> 5;
    int base = blockIdx.x * 128;

    // --- A tile: each thread converts half a row (32 floats) ---
    {
        int r    = t >> 1;
        int coff = (t & 1) * 32;
        int node = base + r;
        const float2* src = (const float2*)(E + (size_t)node * 64 + coff);
        __nv_bfloat16* dh = Ah + r * AS + coff;
        __nv_bfloat16* dl = Al + r * AS + coff;
        if (node < N_NODES) {
            #pragma unroll
            for (int i = 0; i < 16; i++) {
                float2 x = src[i];
                __nv_bfloat162 h = __float22bfloat162_rn(x);
                float2 hf = __bfloat1622float2(h);
                __nv_bfloat162 l = __float22bfloat162_rn(
                    make_float2(x.x - hf.x, x.y - hf.y));
                *(__nv_bfloat162*)(dh + 2 * i) = h;
                *(__nv_bfloat162*)(dl + 2 * i) = l;
            }
        } else {
            #pragma unroll
            for (int i = 0; i < 16; i++) {
                *(__nv_bfloat162*)(dh + 2 * i) = __nv_bfloat162(0.f, 0.f);
                *(__nv_bfloat162*)(dl + 2 * i) = __nv_bfloat162(0.f, 0.f);
            }
        }
    }

    // --- B tiles: vectorized copy of pre-converted weights ---
    for (int v = t; v < 1536; v += 256) {
        int m  = v >> 9;
        int rm = v & 511;
        int n  = rm >> 3;
        int k8 = rm & 7;
        int soff = m * 64 * BS + n * BS + k8 * 8;
        *(uint4*)(Bh + soff) = ((const uint4*)g_Wbh)[v];
        *(uint4*)(Bl + soff) = ((const uint4*)g_Wbl)[v];
    }
    __syncthreads();

    // --- A fragments: load once, reuse for all 3 matrices ---
    wmma::fragment<wmma::matrix_a, 16, 16, 16, __nv_bfloat16, wmma::row_major>
        ah[4], al[4];
    #pragma unroll
    for (int k = 0; k < 4; k++) {
        wmma::load_matrix_sync(ah[k], Ah + (w * 16) * AS + k * 16, AS);
        wmma::load_matrix_sync(al[k], Al + (w * 16) * AS + k * 16, AS);
    }

    #pragma unroll
    for (int m = 0; m < 3; m++) {
        const __nv_bfloat16* BH = Bh + m * 64 * BS;
        const __nv_bfloat16* BL = Bl + m * 64 * BS;

        wmma::fragment<wmma::accumulator, 16, 16, 16, float> acc[4];
        #pragma unroll
        for (int n = 0; n < 4; n++) wmma::fill_fragment(acc[n], 0.0f);

        #pragma unroll
        for (int k = 0; k < 4; k++) {
            #pragma unroll
            for (int n = 0; n < 4; n++) {
                wmma::fragment<wmma::matrix_b, 16, 16, 16, __nv_bfloat16,
                               wmma::col_major> bh, bl;
                wmma::load_matrix_sync(bh, BH + (n * 16) * BS + k * 16, BS);
                wmma::load_matrix_sync(bl, BL + (n * 16) * BS + k * 16, BS);
                wmma::mma_sync(acc[n], ah[k], bh, acc[n]);
                wmma::mma_sync(acc[n], ah[k], bl, acc[n]);
                wmma::mma_sync(acc[n], al[k], bh, acc[n]);
            }
        }

        float* O = (m == 0) ? g_Q : (m == 1) ? g_K : g_V;
        #pragma unroll
        for (int n = 0; n < 4; n++)
            wmma::store_matrix_sync(O + (size_t)(base + w * 16) * 64 + n * 16,
                                    acc[n], 64, wmma::mem_row_major);
    }
}

#define SMEM_WMMA ((2 * 128 * AS + 2 * 3 * 64 * BS) * (int)sizeof(__nv_bfloat16))

// ---------------------------------------------------------------------------
// CSR build: histogram -> block scan -> fix (inline top-prefix) -> scatter
// ---------------------------------------------------------------------------
__global__ void hist_kernel(const int* __restrict__ rows) {
    int e = blockIdx.x * blockDim.x + threadIdx.x;
    if (e < N_EDGES) atomicAdd(&g_deg[rows[e]], 1);
}

__global__ void scan_blocks() {
    int i    = blockIdx.x * 256 + threadIdx.x;
    int lane = threadIdx.x & 31, wid = threadIdx.x >> 5;
    int v = (i < N_NODES) ? g_deg[i] : 0;
    #pragma unroll
    for (int o = 1; o < 32; o <<= 1) {
        int u = __shfl_up_sync(0xffffffffu, v, o);
        if (lane >= o) v += u;
    }
    __shared__ int ws[8];
    if (lane == 31) ws[wid] = v;
    __syncthreads();
    if (wid == 0 && lane < 8) {
        int x = ws[lane];
        #pragma unroll
        for (int o = 1; o < 8; o <<= 1) {
            int u = __shfl_up_sync(0xffu, x, o);
            if (lane >= o) x += u;
        }
        ws[lane] = x;
    }
    __syncthreads();
    if (wid > 0) v += ws[wid - 1];
    g_incl[blockIdx.x * 256 + threadIdx.x] = v;
    if (threadIdx.x == 255) g_bsum[blockIdx.x] = v;
}

// scan_fix with inlined top-level prefix: each block sums bsum[0..blockIdx)
__global__ void scan_fix() {
    __shared__ int s_off;
    __shared__ int ws[8];
    int t = threadIdx.x, lane = t & 31, wid = t >> 5;

    int partial = 0;
    for (int i = t; i < blockIdx.x; i += 256) partial += g_bsum[i];
    #pragma unroll
    for (int o = 16; o > 0; o >>= 1)
        partial += __shfl_down_sync(0xffffffffu, partial, o);
    if (lane == 0) ws[wid] = partial;
    __syncthreads();
    if (t == 0) {
        int tot = 0;
        #pragma unroll
        for (int k = 0; k < 8; k++) tot += ws[k];
        s_off = tot;
    }
    __syncthreads();

    int i = blockIdx.x * 256 + t;
    if (i >= N_NODES) return;
    int st = g_incl[i] + s_off - g_deg[i];
    g_start[i]  = st;
    g_cursor[i] = st;
}

__global__ void scatter_kernel(const int* __restrict__ rows,
                               const int* __restrict__ cols) {
    int e = blockIdx.x * blockDim.x + threadIdx.x;
    if (e >= N_EDGES) return;
    int r = rows[e];
    int p = atomicAdd(&g_cursor[r], 1);
    g_colS[p] = cols[e];
    g_perm[p] = e;
}

// ---------------------------------------------------------------------------
// Half-warp-per-node fused attention (R15). 16 lanes per node; lane owns 4
// dims (head = l>>2, float4 K/V loads, 2-shfl dot). Two nodes per warp in
// lockstep. Also restores g_deg[n]=0 for the next run (replaces memset).
// ---------------------------------------------------------------------------
__global__ __launch_bounds__(64) void node_attn(float* __restrict__ res,
                                                float* __restrict__ att) {
    int tid  = threadIdx.x;
    int node = blockIdx.x * 4 + (tid >> 4);
    bool vn  = node < N_NODES;
    int n = vn ? node : 0;
    int l = tid & 15;                 // lane within half-warp
    int h = l >> 2;                   // head (4 lanes per head)
    int s = g_start[n];
    int d = vn ? g_deg[n] : 0;
    if (vn && l == 0) g_deg[n] = 0;   // restore invariant for next replay
    int dmax = max(d, __shfl_xor_sync(0xffffffffu, d, 16));

    float4 q4 = *(const float4*)&g_Q[(size_t)n * DIM + l * 4];
    float4 acc = make_float4(0.f, 0.f, 0.f, 0.f);
    float norm = 0.f;
    bool leader = (l & 3) == 0;

    for (int j = 0; j < dmax; j += 4) {
        bool va[4];
        int  idx[4], cc[4];
        #pragma unroll
        for (int i = 0; i < 4; i++) {
            va[i]  = (j + i) < d;
            idx[i] = va[i] ? (s + j + i) : 0;      // safe dummy
        }
        #pragma unroll
        for (int i = 0; i < 4; i++) cc[i] = g_colS[idx[i]];
        float4 kk[4], vv[4];
        #pragma unroll
        for (int i = 0; i < 4; i++) {
            kk[i] = *(const float4*)&g_K[(size_t)cc[i] * DIM + l * 4];
            vv[i] = *(const float4*)&g_V[(size_t)cc[i] * DIM + l * 4];
        }
        #pragma unroll
        for (int i = 0; i < 4; i++) {
            float p = kk[i].x * q4.x + kk[i].y * q4.y
                    + kk[i].z * q4.z + kk[i].w * q4.w;
            p += __shfl_xor_sync(0xffffffffu, p, 1);
            p += __shfl_xor_sync(0xffffffffu, p, 2);
            float ex = va[i] ? __expf(fminf(fmaxf(p, -10.f), 10.f)) : 0.f;
            norm += ex;
            acc.x = fmaf(ex, vv[i].x, acc.x);
            acc.y = fmaf(ex, vv[i].y, acc.y);
            acc.z = fmaf(ex, vv[i].z, acc.z);
            acc.w = fmaf(ex, vv[i].w, acc.w);
            if (va[i] && leader) att[g_perm[idx[i]] * 4 + h] = ex;
        }
    }

    float inv = 1.0f / (norm + 1e-8f);
    if (vn)
        *(float4*)&res[(size_t)n * DIM + l * 4] =
            make_float4(acc.x * inv, acc.y * inv, acc.z * inv, acc.w * inv);

    // normalize this node's att entries (16-lane strided per half)
    int hb = tid & 16;                // half base within warp (0 or 16)
    float i0 = __shfl_sync(0xffffffffu, inv, hb + 0);
    float i1 = __shfl_sync(0xffffffffu, inv, hb + 4);
    float i2 = __shfl_sync(0xffffffffu, inv, hb + 8);
    float i3 = __shfl_sync(0xffffffffu, inv, hb + 12);
    for (int jj = l; jj < d; jj += 16) {
        int e = g_perm[s + jj];
        float4 a = *(float4*)&att[e * 4];
        a.x *= i0; a.y *= i1; a.z *= i2; a.w *= i3;
        *(float4*)&att[e * 4] = a;
    }
}

// ---------------------------------------------------------------------------
extern "C" void kernel_launch(void* const* d_in, const int* in_sizes, int n_in,
                              void* d_out, int out_size) {
    const float* embeds = (const float*)d_in[0];
    const float* Wq     = (const float*)d_in[1];
    const float* Wk     = (const float*)d_in[2];
    const float* Wv     = (const float*)d_in[3];
    const int*   rows   = (const int*)d_in[4];
    const int*   cols   = (const int*)d_in[5];

    float* res = (float*)d_out;                    // [N_NODES, 64]
    float* att = (float*)d_out + N_NODES * DIM;    // [N_EDGES, 4]

    static cudaStream_t sCsr = nullptr;
    static cudaEvent_t  evFork = nullptr, evJoin = nullptr;
    if (sCsr == nullptr) {
        cudaStreamCreateWithFlags(&sCsr, cudaStreamNonBlocking);
        cudaEventCreateWithFlags(&evFork, cudaEventDisableTiming);
        cudaEventCreateWithFlags(&evJoin, cudaEventDisableTiming);
    }

    // Fork: CSR chain (rows/cols only) parallel to tensor-core GEMM.
    cudaEventRecord(evFork, 0);
    cudaStreamWaitEvent(sCsr, evFork, 0);

    // Branch A (stream 0): W pre-convert + wmma QKV projection
    wconv<<<48, 256>>>(Wq, Wk, Wv);
    cudaFuncSetAttribute(gemm_qkv_wmma,
                         cudaFuncAttributeMaxDynamicSharedMemorySize, SMEM_WMMA);
    gemm_qkv_wmma<<<(N_NODES + 127) / 128, 256, SMEM_WMMA>>>(embeds);

    // Branch B (sCsr): CSR build (no memset: g_deg restored by node_attn)
    int eb = (N_EDGES + 255) / 256;
    hist_kernel<<<eb, 256, 0, sCsr>>>(rows);
    scan_blocks<<<NBLK, 256, 0, sCsr>>>();
    scan_fix<<<NBLK, 256, 0, sCsr>>>();
    scatter_kernel<<<eb, 256, 0, sCsr>>>(rows, cols);

    // Join
    cudaEventRecord(evJoin, sCsr);
    cudaStreamWaitEvent(0, evJoin, 0);

    // fused attention: logits + softmax + aggregate + att normalize
    node_attn<<<(N_NODES + 3) / 4, 64>>>(res, att);
}